// round 7
// baseline (speedup 1.0000x reference)
#include <cuda_runtime.h>
#include <cuda_bf16.h>
#include <cuda_fp16.h>
#include <math.h>
#include <stdint.h>

#define Bb   2
#define Tt   2048
#define Cc   2048
#define NH   16
#define NKV  4
#define HD   128
#define QDIM (NH * HD)    // 2048
#define KDIM (NKV * HD)   // 512
#define NALL (QDIM + 2 * KDIM)   // 3072 fused projection width
#define MROWS (Bb * Tt)   // 4096

// ------------------------- device scratch (no allocs allowed) --------------
__device__ float2 g_rope[Tt * 64];
__device__ __half g_xh[(size_t)MROWS * Cc];
__device__ __half g_QKVh[(size_t)MROWS * NALL];
__device__ __half g_Oh[(size_t)MROWS * QDIM];
__device__ __half g_wAllT[(size_t)NALL * Cc];   // packed wq^T | wk^T | wv^T (fp16, K-contig)
__device__ __half g_woT[(size_t)Cc * QDIM];

// ------------------------- PTX helpers (sm_80-era, base-target-safe) -------
__device__ __forceinline__ uint32_t smem_u32(const void* p) {
    uint32_t a;
    asm("{ .reg .u64 t; cvta.to.shared.u64 t, %1; cvt.u32.u64 %0, t; }" : "=r"(a) : "l"(p));
    return a;
}
__device__ __forceinline__ void cp16(uint32_t saddr, const void* g) {
    asm volatile("cp.async.cg.shared.global [%0], [%1], 16;" :: "r"(saddr), "l"(g));
}
#define CP_COMMIT() asm volatile("cp.async.commit_group;" ::: "memory")
template <int N> __device__ __forceinline__ void cp_wait() {
    asm volatile("cp.async.wait_group %0;" :: "n"(N) : "memory");
}
__device__ __forceinline__ void ldsm4(uint32_t* r, uint32_t addr) {
    asm volatile("ldmatrix.sync.aligned.m8n8.x4.shared.b16 {%0,%1,%2,%3}, [%4];"
                 : "=r"(r[0]), "=r"(r[1]), "=r"(r[2]), "=r"(r[3]) : "r"(addr));
}
__device__ __forceinline__ void ldsm4t(uint32_t* r, uint32_t addr) {
    asm volatile("ldmatrix.sync.aligned.m8n8.x4.trans.shared.b16 {%0,%1,%2,%3}, [%4];"
                 : "=r"(r[0]), "=r"(r[1]), "=r"(r[2]), "=r"(r[3]) : "r"(addr));
}
// NOTE: NOT volatile — register-only side effects; lets ptxas software-pipeline
// MMAs past subsequent LDSMs (deps carried entirely through registers).
__device__ __forceinline__ void mma16816h(float* d, const uint32_t* a, const uint32_t* b) {
    asm("mma.sync.aligned.m16n8k16.row.col.f32.f16.f16.f32 "
        "{%0,%1,%2,%3}, {%4,%5,%6,%7}, {%8,%9}, {%0,%1,%2,%3};"
        : "+f"(d[0]), "+f"(d[1]), "+f"(d[2]), "+f"(d[3])
        : "r"(a[0]), "r"(a[1]), "r"(a[2]), "r"(a[3]), "r"(b[0]), "r"(b[1]));
}
__device__ __forceinline__ uint32_t swz128(uint32_t o) { return o ^ ((o >> 3) & 0x70); }

// ------------------------- prep kernels ------------------------------------
__global__ void to_f16(const float* __restrict__ src, __half* __restrict__ dst, int n4) {
    int i = blockIdx.x * blockDim.x + threadIdx.x;
    if (i >= n4) return;
    float4 v = ((const float4*)src)[i];
    __half2* d = (__half2*)dst;
    d[i * 2]     = __floats2half2_rn(v.x, v.y);
    d[i * 2 + 1] = __floats2half2_rn(v.z, v.w);
}

// all 4 weight transposes in one launch; z selects matrix. fp32 [K,N] -> fp16 [N,K]
__global__ void transpose_f16_all(const float* __restrict__ wq, const float* __restrict__ wk,
                                  const float* __restrict__ wv, const float* __restrict__ wo,
                                  __half* __restrict__ wallT, __half* __restrict__ woT)
{
    __shared__ float t[32][33];
    const int z = blockIdx.z;
    const float* src; __half* dst; int N, rowoff;
    if (z == 0)      { src = wq; N = QDIM; rowoff = 0;    dst = wallT; }
    else if (z == 1) { src = wk; N = KDIM; rowoff = 2048; dst = wallT; }
    else if (z == 2) { src = wv; N = KDIM; rowoff = 2560; dst = wallT; }
    else             { src = wo; N = QDIM; rowoff = 0;    dst = woT;   }
    const int n0 = blockIdx.x * 32;
    if (n0 >= N) return;
    const int k0 = blockIdx.y * 32;
    const int tx = threadIdx.x, ty = threadIdx.y;  // 32x8
#pragma unroll
    for (int i = 0; i < 4; i++)
        t[ty + 8 * i][tx] = src[(size_t)(k0 + ty + 8 * i) * N + n0 + tx];
    __syncthreads();
#pragma unroll
    for (int i = 0; i < 4; i++)
        dst[(size_t)(rowoff + n0 + ty + 8 * i) * Cc + k0 + tx] =
            __float2half_rn(t[tx][ty + 8 * i]);
}

__global__ void rope_table_kernel() {
    const int i = blockIdx.x * blockDim.x + threadIdx.x;
    if (i >= Tt * 64) return;
    const int t = i >> 6, f = i & 63;
    double inv = exp(-(double)f * 0.14391156831212787);  // ln(10000)/64
    double a = (double)t * inv;
    g_rope[i] = make_float2((float)sin(a), (float)cos(a));
}

// in-place rope on fused fp16 QKV (q and k columns only)
__global__ void rope_f16(__half* __restrict__ QKV) {
    const int idx = blockIdx.x * blockDim.x + threadIdx.x;
    const int nq = MROWS * NH * 64;
    const int nk = MROWS * NKV * 64;
    if (idx >= nq + nk) return;
    int f, bt, col;
    if (idx < nq) {
        f = idx & 63;
        int h = (idx >> 6) & (NH - 1);
        bt = idx >> 10;
        col = h * HD + f;
    } else {
        int k = idx - nq;
        f = k & 63;
        int h = (k >> 6) & (NKV - 1);
        bt = k >> 8;
        col = 2048 + h * HD + f;
    }
    const float2 sc = g_rope[(bt & (Tt - 1)) * 64 + f];
    const size_t base = (size_t)bt * NALL + col;
    const float x1 = __half2float(QKV[base]);
    const float x2 = __half2float(QKV[base + 64]);
    QKV[base]      = __float2half_rn(x1 * sc.y - x2 * sc.x);
    QKV[base + 64] = __float2half_rn(x2 * sc.y + x1 * sc.x);
}

// ------------------------- single-term fp16 HMMA GEMM -----------------------
// C[M,N] = A * B^T ; A [M,K] fp16 K-contig, B [N,K] fp16 K-contig.
// CTA tile 128x128, K-chunk 64 (128B rows, SW128), 3-stage cp.async pipeline.
#define GSMEM (3 * 32768 + 128)
template <typename OutT>
__global__ __launch_bounds__(256, 2) void gemm_f16(
    const __half* __restrict__ A, const __half* __restrict__ Bm,
    OutT* __restrict__ C, int Cstride, int Kdim)
{
    extern __shared__ char smraw[];
    const uint32_t sb = (smem_u32(smraw) + 127) & ~127u;
    const int tid = threadIdx.x;
    const int lane = tid & 31, wid = tid >> 5;
    const int wm = wid >> 1, wn = wid & 1;
    const int bm = blockIdx.y * 128, bn = blockIdx.x * 128;

    float acc[2][8][4];
#pragma unroll
    for (int i = 0; i < 2; i++)
#pragma unroll
        for (int t = 0; t < 8; t++)
#pragma unroll
            for (int e = 0; e < 4; e++) acc[i][t][e] = 0.0f;

    const int nch = Kdim >> 6;

    auto prefetch = [&](int ch) {
        const uint32_t st = sb + (ch % 3) * 32768;
        const int kc = ch << 6;
#pragma unroll
        for (int q = 0; q < 4; q++) {
            int idx = tid + q * 256;
            int r = idx >> 3, u = idx & 7;
            uint32_t so = swz128((uint32_t)(r * 128 + u * 16));
            cp16(st + so,         A  + (size_t)(bm + r) * Kdim + kc + u * 8);
            cp16(st + 16384 + so, Bm + (size_t)(bn + r) * Kdim + kc + u * 8);
        }
        CP_COMMIT();
    };

    prefetch(0);
    prefetch(1);
    const uint32_t arow = wm * 32 + (lane & 15);
    const uint32_t acb  = ((uint32_t)(lane >> 4)) << 4;
    const uint32_t brow = wn * 64 + (lane & 7) + (((uint32_t)(lane >> 4)) << 3);
    const uint32_t bcb  = (((uint32_t)(lane >> 3)) & 1u) << 4;

    for (int ch = 0; ch < nch; ch++) {
        if (ch + 2 < nch) { prefetch(ch + 2); cp_wait<2>(); }
        else if (ch + 1 < nch) cp_wait<1>();
        else cp_wait<0>();
        __syncthreads();
        const uint32_t st = sb + (ch % 3) * 32768;
#pragma unroll
        for (int s = 0; s < 4; s++) {
            const uint32_t kb = s * 32;
            uint32_t ah[2][4], bh[4][4];
#pragma unroll
            for (int i = 0; i < 2; i++)
                ldsm4(ah[i], st + swz128((arow + i * 16) * 128 + kb + acb));
#pragma unroll
            for (int j = 0; j < 4; j++)
                ldsm4(bh[j], st + 16384 + swz128((brow + j * 16) * 128 + kb + bcb));
#pragma unroll
            for (int i = 0; i < 2; i++)
#pragma unroll
                for (int t = 0; t < 8; t++)
                    mma16816h(acc[i][t], ah[i], &bh[t >> 1][(t & 1) * 2]);
        }
        __syncthreads();
    }

#pragma unroll
    for (int i = 0; i < 2; i++) {
        const int r0 = bm + wm * 32 + i * 16 + (lane >> 2);
#pragma unroll
        for (int t = 0; t < 8; t++) {
            const int c = bn + wn * 64 + t * 8 + (lane & 3) * 2;
            if constexpr (sizeof(OutT) == 2) {
                *(__half2*)(C + (size_t)r0 * Cstride + c) =
                    __floats2half2_rn(acc[i][t][0], acc[i][t][1]);
                *(__half2*)(C + (size_t)(r0 + 8) * Cstride + c) =
                    __floats2half2_rn(acc[i][t][2], acc[i][t][3]);
            } else {
                *(float2*)(C + (size_t)r0 * Cstride + c) =
                    make_float2(acc[i][t][0], acc[i][t][1]);
                *(float2*)(C + (size_t)(r0 + 8) * Cstride + c) =
                    make_float2(acc[i][t][2], acc[i][t][3]);
            }
        }
    }
}

// ------------------------- fp16 HMMA flash attention -----------------------
// Row stats (m, l) live in REGISTERS, replicated across the quad and the wn
// warp pair; only quad-reduced pmax/psum go through smem. 4 barriers per tile.
#define SQ  0
#define SK  32768
#define SV  65536
#define SP  98304
#define SRED 131072
#define ATT_SMEM (SRED + 512 * 4)   // pmax[2][128], psum[2][128]

__global__ __launch_bounds__(256) void attn_hmma(
    const __half* __restrict__ QKV, __half* __restrict__ Oh)
{
    extern __shared__ char smraw[];
    const uint32_t sb = smem_u32(smraw);
    float* pmax = (float*)(smraw + SRED);   // [2][128]
    float* psum = pmax + 256;               // [2][128]

    const int tid = threadIdx.x, lane = tid & 31, wid = tid >> 5;
    const int wm = wid >> 1, wn = wid & 1;
    const int qt = (int)gridDim.x - 1 - (int)blockIdx.x;   // heavy tiles first
    const int g = blockIdx.y, b = blockIdx.z;
    const int kvh = g & (NKV - 1);
    const int q0 = qt * 128;
    const size_t qrow = (size_t)(b * Tt + q0);

    auto loadQ = [&]() {
        const __half* gq = QKV + qrow * NALL + g * HD;
#pragma unroll
        for (int q = 0; q < 8; q++) {
            int idx = tid + q * 256;
            int r = idx >> 4, u = idx & 15;
            uint32_t so = ((uint32_t)(u >> 3) << 14) + swz128((uint32_t)(r * 128 + (u & 7) * 16));
            cp16(sb + SQ + so, gq + (size_t)r * NALL + u * 8);
        }
        CP_COMMIT();
    };
    auto loadK = [&](int kt) {
        const __half* gk = QKV + (size_t)(b * Tt + kt * 128) * NALL + 2048 + kvh * HD;
#pragma unroll
        for (int q = 0; q < 8; q++) {
            int idx = tid + q * 256;
            int r = idx >> 4, u = idx & 15;
            uint32_t so = ((uint32_t)(u >> 3) << 14) + swz128((uint32_t)(r * 128 + (u & 7) * 16));
            cp16(sb + SK + so, gk + (size_t)r * NALL + u * 8);
        }
        CP_COMMIT();
    };
    auto loadV = [&](int kt) {
        const __half* gv = QKV + (size_t)(b * Tt + kt * 128) * NALL + 2560 + kvh * HD;
#pragma unroll
        for (int q = 0; q < 8; q++) {
            int idx = tid + q * 256;
            int r = idx >> 4, u = idx & 15;
            uint32_t so = ((uint32_t)(u >> 3) << 14) + swz128((uint32_t)(r * 128 + (u & 7) * 16));
            cp16(sb + SV + so, gv + (size_t)r * NALL + u * 8);
        }
        CP_COMMIT();
    };

    loadQ();
    loadK(0);

    float o[2][8][4];
#pragma unroll
    for (int i = 0; i < 2; i++)
#pragma unroll
        for (int t = 0; t < 8; t++)
#pragma unroll
            for (int e = 0; e < 4; e++) o[i][t][e] = 0.0f;

    float m_r[2][2] = {{-INFINITY, -INFINITY}, {-INFINITY, -INFINITY}};
    float l_r[2][2] = {{0.f, 0.f}, {0.f, 0.f}};

    const float pre = 0.08838834764831843f * 0.02f;  // (1/sqrt(128)) / 50

    for (int kt = 0; kt <= qt; kt++) {
        __syncthreads();                 // (a) prev PV readers of sV/sP done
        loadV(kt);
        cp_wait<1>();                    // Q + K(kt) arrived (V pending ok)
        __syncthreads();                 // (b)

        // ---- S = Q K^T
        float s[2][8][4];
#pragma unroll
        for (int i = 0; i < 2; i++)
#pragma unroll
            for (int t = 0; t < 8; t++)
#pragma unroll
                for (int e = 0; e < 4; e++) s[i][t][e] = 0.0f;

#pragma unroll
        for (int ks = 0; ks < 8; ks++) {
            uint32_t ah[2][4];
#pragma unroll
            for (int i = 0; i < 2; i++) {
                uint32_t c = ks * 32 + ((uint32_t)(lane >> 4) << 4);
                uint32_t row = wm * 32 + i * 16 + (lane & 15);
                uint32_t off = ((c >> 7) << 14) + swz128(row * 128 + (c & 127));
                ldsm4(ah[i], sb + SQ + off);
            }
#pragma unroll
            for (int jt = 0; jt < 4; jt++) {
                uint32_t bh[4];
                uint32_t c = ks * 32 + (((uint32_t)(lane >> 3) & 1u) << 4);
                uint32_t j = wn * 64 + jt * 16 + (lane & 7) + ((uint32_t)(lane >> 4) << 3);
                uint32_t off = ((c >> 7) << 14) + swz128(j * 128 + (c & 127));
                ldsm4(bh, sb + SK + off);
#pragma unroll
                for (int i = 0; i < 2; i++)
#pragma unroll
                    for (int sub = 0; sub < 2; sub++)
                        mma16816h(s[i][jt * 2 + sub], ah[i], bh + sub * 2);
            }
        }

        // ---- softcap (poly tanh) + causal mask + quad row-max -> pmax
        const bool diag = (kt == qt);
        float rmx[2][2] = {{-INFINITY, -INFINITY}, {-INFINITY, -INFINITY}};
#pragma unroll
        for (int i = 0; i < 2; i++)
#pragma unroll
            for (int t = 0; t < 8; t++)
#pragma unroll
                for (int e = 0; e < 4; e++) {
                    float x = s[i][t][e] * pre;
                    float x2 = x * x;
                    float th = x * (1.0f + x2 * (-0.33333333f + x2 * (0.13333333f - 0.05396825f * x2)));
                    float v = 50.0f * th;
                    if (diag) {
                        int r  = wm * 32 + i * 16 + (lane >> 2) + ((e >> 1) << 3);
                        int cc = wn * 64 + t * 8 + ((lane & 3) << 1) + (e & 1);
                        if (cc > r) v = -1e30f;
                    }
                    s[i][t][e] = v;
                    rmx[i][e >> 1] = fmaxf(rmx[i][e >> 1], v);
                }
#pragma unroll
        for (int i = 0; i < 2; i++)
#pragma unroll
            for (int h = 0; h < 2; h++) {
                float m = rmx[i][h];
                m = fmaxf(m, __shfl_xor_sync(0xffffffffu, m, 1));
                m = fmaxf(m, __shfl_xor_sync(0xffffffffu, m, 2));
                if ((lane & 3) == 0)
                    pmax[wn * 128 + wm * 32 + i * 16 + h * 8 + (lane >> 2)] = m;
            }
        __syncthreads();                 // (c) sK consumed; pmax visible

        if (kt < qt) loadK(kt + 1);      // prefetch next K

        // ---- per-thread stats update (register m, corr)
        float corr[2][2];
#pragma unroll
        for (int i = 0; i < 2; i++)
#pragma unroll
            for (int h = 0; h < 2; h++) {
                int r = wm * 32 + i * 16 + h * 8 + (lane >> 2);
                float mo = m_r[i][h];
                float mn = fmaxf(mo, fmaxf(pmax[r], pmax[128 + r]));
                corr[i][h] = __expf(mo - mn);
                m_r[i][h] = mn;
            }

        // ---- p = exp(s - m) -> fp16 sP; quad row-sums -> psum; rescale O
        float rsum[2][2] = {{0.f, 0.f}, {0.f, 0.f}};
#pragma unroll
        for (int i = 0; i < 2; i++)
#pragma unroll
            for (int h = 0; h < 2; h++) {
                int r = wm * 32 + i * 16 + h * 8 + (lane >> 2);
                float mr = m_r[i][h];
                float cr = corr[i][h];
#pragma unroll
                for (int t = 0; t < 8; t++) {
                    float p0 = __expf(s[i][t][h * 2 + 0] - mr);
                    float p1 = __expf(s[i][t][h * 2 + 1] - mr);
                    rsum[i][h] += p0 + p1;
                    uint32_t cb = (uint32_t)(t * 8 + ((lane & 3) << 1)) * 2;
                    uint32_t off = ((uint32_t)wn << 14) + swz128((uint32_t)r * 128 + cb);
                    *(__half2*)(smraw + SP + off) = __floats2half2_rn(p0, p1);
                    o[i][t][h * 2 + 0] *= cr;
                    o[i][t][h * 2 + 1] *= cr;
                }
                l_r[i][h] *= cr;
            }
#pragma unroll
        for (int i = 0; i < 2; i++)
#pragma unroll
            for (int h = 0; h < 2; h++) {
                float sv = rsum[i][h];
                sv += __shfl_xor_sync(0xffffffffu, sv, 1);
                sv += __shfl_xor_sync(0xffffffffu, sv, 2);
                if ((lane & 3) == 0)
                    psum[wn * 128 + wm * 32 + i * 16 + h * 8 + (lane >> 2)] = sv;
            }
        if (kt < qt) cp_wait<1>();       // V(kt) done (K(kt+1) pending ok)
        else         cp_wait<0>();
        __syncthreads();                 // (e) sV + sP + psum visible
#pragma unroll
        for (int i = 0; i < 2; i++)
#pragma unroll
            for (int h = 0; h < 2; h++) {
                int r = wm * 32 + i * 16 + h * 8 + (lane >> 2);
                l_r[i][h] += psum[r] + psum[128 + r];
            }

        // ---- O += P V
#pragma unroll
        for (int ks = 0; ks < 8; ks++) {
            uint32_t ph[2][4];
#pragma unroll
            for (int i = 0; i < 2; i++) {
                uint32_t c = ks * 32 + ((uint32_t)(lane >> 4) << 4);
                uint32_t row = wm * 32 + i * 16 + (lane & 15);
                uint32_t off = ((c >> 7) << 14) + swz128(row * 128 + (c & 127));
                ldsm4(ph[i], sb + SP + off);
            }
#pragma unroll
            for (int dt = 0; dt < 4; dt++) {
                uint32_t vh[4];
                uint32_t dbase = wn * 64 + dt * 16 + ((uint32_t)(lane >> 4) << 3);
                uint32_t j = ks * 16 + (lane & 15);
                uint32_t off = ((dbase >> 6) << 14) + swz128(j * 128 + (dbase & 63) * 2);
                ldsm4t(vh, sb + SV + off);
#pragma unroll
                for (int i = 0; i < 2; i++)
#pragma unroll
                    for (int sub = 0; sub < 2; sub++)
                        mma16816h(o[i][dt * 2 + sub], ph[i], vh + sub * 2);
            }
        }
    }

    // ---- epilogue: normalize (l in registers), write O fp16
#pragma unroll
    for (int i = 0; i < 2; i++)
#pragma unroll
        for (int h = 0; h < 2; h++) {
            int r = wm * 32 + i * 16 + h * 8 + (lane >> 2);
            float inv = 1.0f / l_r[i][h];
            size_t gro = (qrow + r) * QDIM + g * HD;
#pragma unroll
            for (int t = 0; t < 8; t++) {
                int cc = wn * 64 + t * 8 + ((lane & 3) << 1);
                *(__half2*)(Oh + gro + cc) = __floats2half2_rn(
                    o[i][t][h * 2 + 0] * inv, o[i][t][h * 2 + 1] * inv);
            }
        }
}

// ---------------------------------------------------------------------------
extern "C" void kernel_launch(void* const* d_in, const int* in_sizes, int n_in,
                              void* d_out, int out_size)
{
    const float* x  = (const float*)d_in[0];
    const float* wq = (const float*)d_in[2];
    const float* wk = (const float*)d_in[3];
    const float* wv = (const float*)d_in[4];
    const float* wo = (const float*)d_in[5];
    float* out = (float*)d_out;

    __half *xh, *qkvh, *oh, *wallT, *woT;
    cudaGetSymbolAddress((void**)&xh, g_xh);
    cudaGetSymbolAddress((void**)&qkvh, g_QKVh);
    cudaGetSymbolAddress((void**)&oh, g_Oh);
    cudaGetSymbolAddress((void**)&wallT, g_wAllT);
    cudaGetSymbolAddress((void**)&woT, g_woT);

    // ---- prep
    {
        int n4 = MROWS * Cc / 4;
        to_f16<<<(n4 + 255) / 256, 256>>>(x, xh, n4);
    }
    transpose_f16_all<<<dim3(QDIM / 32, Cc / 32, 4), dim3(32, 8)>>>(
        wq, wk, wv, wo, wallT, woT);
    rope_table_kernel<<<(Tt * 64 + 255) / 256, 256>>>();

    // ---- fused QKV projection (fp16 HMMA) -> fp16 QKV
    cudaFuncSetAttribute(gemm_f16<__half>, cudaFuncAttributeMaxDynamicSharedMemorySize, GSMEM);
    cudaFuncSetAttribute(gemm_f16<float>, cudaFuncAttributeMaxDynamicSharedMemorySize, GSMEM);
    gemm_f16<__half><<<dim3(NALL / 128, MROWS / 128), 256, GSMEM>>>(
        xh, wallT, qkvh, NALL, Cc);

    // ---- rope in-place on q/k columns
    {
        const int pairs = MROWS * (NH + NKV) * 64;
        rope_f16<<<(pairs + 255) / 256, 256>>>(qkvh);
    }

    // ---- attention (fp16 HMMA, reads strided from fused QKV)
    cudaFuncSetAttribute(attn_hmma, cudaFuncAttributeMaxDynamicSharedMemorySize, ATT_SMEM);
    attn_hmma<<<dim3(Tt / 128, NH, Bb), 256, ATT_SMEM>>>(qkvh, oh);

    // ---- output projection (fp16 HMMA) -> fp32 out
    gemm_f16<float><<<dim3(QDIM / 128, MROWS / 128), 256, GSMEM>>>(
        oh, woT, out, QDIM, Cc);
}